// round 14
// baseline (speedup 1.0000x reference)
#include <cuda_runtime.h>
#include <cuda_bf16.h>
#include <math.h>
#include <float.h>

typedef unsigned long long ull;
typedef unsigned int u32;

#define N_POOL   2048
#define D_SP     64
#define ROWS_TOT 8192
#define D_MODEL_ 1024
#define PROJ_COLS 384
#define TPAIR    8           // pairs kept per quad-lane (provably sufficient)
#define CAND_ROW 32          // 4 lanes * TPAIR pair entries per row

// ---------------- scratch ----------------
__device__ float g_proj[ROWS_TOT * PROJ_COLS];                       // 12.6 MB
__device__ __align__(128) __nv_bfloat16 g_ehi[4 * N_POOL * D_SP];    // 1 MB  bf16 [n][64] (MMA-frag permuted)
__device__ __align__(128) float g_enorm[4 * N_POOL * D_SP];          // 2 MB  fp32 [n][64] (original order)
__device__ u32   g_cand[6 * ROWS_TOT * CAND_ROW];                    // 6.3 MB (pair base cols)
__device__ float g_z[6 * ROWS_TOT * 4];                              // 0.8 MB

__constant__ int c_pool[6] = {0, 0, 1, 2, 2, 3};

// ---------------- f32x2 helpers (proj phase) ----------------
__device__ __forceinline__ ull pack2(float lo, float hi) {
    ull u; asm("mov.b64 %0, {%1, %2};" : "=l"(u) : "f"(lo), "f"(hi)); return u;
}
__device__ __forceinline__ float2 unpack2(ull u) {
    float2 v; asm("mov.b64 {%0, %1}, %2;" : "=f"(v.x), "=f"(v.y) : "l"(u)); return v;
}
__device__ __forceinline__ ull ffma2(ull a, ull b, ull c) {
    ull d; asm("fma.rn.f32x2 %0, %1, %2, %3;" : "=l"(d) : "l"(a), "l"(b), "l"(c)); return d;
}

// ---------------- mma.sync m16n8k16 bf16 (HMMA fallback on sm_103) ----------------
__device__ __forceinline__ void mma16816(float (&d)[4], const u32 (&a)[4], u32 b0, u32 b1) {
    asm volatile(
        "mma.sync.aligned.m16n8k16.row.col.f32.bf16.bf16.f32 "
        "{%0,%1,%2,%3}, {%4,%5,%6,%7}, {%8,%9}, {%0,%1,%2,%3};"
        : "+f"(d[0]), "+f"(d[1]), "+f"(d[2]), "+f"(d[3])
        : "r"(a[0]), "r"(a[1]), "r"(a[2]), "r"(a[3]), "r"(b0), "r"(b1));
}

// ---------------- bf16 helper ----------------
__device__ __forceinline__ u32 bf16x2_hi(float x, float y) {
    __nv_bfloat16 hx = __float2bfloat16(x), hy = __float2bfloat16(y);
    return (u32)__bfloat16_as_ushort(hx) | ((u32)__bfloat16_as_ushort(hy) << 16);
}

// ---------------- ordered-float packed key ----------------
__device__ __forceinline__ u32 make_key(float v, u32 inv_p) {
    u32 u = __float_as_uint(v);
    u ^= ((u32)(((int)u) >> 31)) | 0x80000000u;     // monotonic transform
    return (u & 0xFFFFFF00u) | inv_p;               // low 8 bits = 255 - pairidx
}

// ---------------- dummy kernel (shifts the fixed ncu capture slot) ----------------
__global__ void k_pre() {}

// ---------------- kernel 1: normalize emb rows -> fp32 (orig order) + bf16 (frag-permuted) ----------------
// bf16 permutation within each 64-elem row: old k = ks*16 + h*8 + q*2 + e  ->
// new kp = ks*16 + q*4 + h*2 + e, so each MMA B-fragment (b0,b1 for fixed ks,q) is 8B-adjacent.
__global__ __launch_bounds__(256) void k_norm(const float* __restrict__ emb) {
    const int tid = threadIdx.x;
    const int n = blockIdx.x * 64 + (tid >> 2);      // neuron 0..8191
    const int q16 = (tid & 3) * 16;
    const float* r = emb + (size_t)n * D_SP + q16;
    float v[16]; float ss = 0.f;
#pragma unroll
    for (int i = 0; i < 16; ++i) { v[i] = r[i]; ss += v[i] * v[i]; }
    ss += __shfl_xor_sync(0xffffffffu, ss, 1);
    ss += __shfl_xor_sync(0xffffffffu, ss, 2);
    const float nrm = fmaxf(sqrtf(ss), 1e-12f);
    float* of = g_enorm + (size_t)n * D_SP + q16;
    __nv_bfloat16* ohb = g_ehi + (size_t)n * D_SP;
#pragma unroll
    for (int i = 0; i < 16; ++i) {
        float x = v[i] / nrm;
        of[i] = x;
        int k = q16 + i;
        int ks = k >> 4, rr = k & 15;
        int h = (rr >> 3) & 1, qq = (rr >> 1) & 3, e = k & 1;
        ohb[ks * 16 + qq * 4 + h * 2 + e] = __float2bfloat16(x);
    }
}

// ---------------- fused kernel: proj (FFMA2, exact) + coarse (bf16 MMA) ----------------
// grid (64, 6), 256 threads. blockIdx.x = 128-row tile, blockIdx.y = chunk c.
#define MROWS 128
#define NTILE 256
#define EPAD  72            // bf16 elements per padded row (144 B)
#define KC    32            // proj K-chunk
#define SMEM_BYTES (NTILE * EPAD * 2)   // 36864; >= proj phase's 16896+8192

__global__ __launch_bounds__(256, 2)
void k_pc(const float* __restrict__ X, const float* __restrict__ W,
          const float* __restrict__ bias) {
    extern __shared__ __align__(16) char smem[];
    float* As = reinterpret_cast<float*>(smem);               // [32][132] = 16896 B
    float* Bs = reinterpret_cast<float*>(smem) + 32 * 132;    // [32][64]  =  8192 B

    const int tid = threadIdx.x;
    const int wid = tid >> 5;
    const int lane = tid & 31;
    const int c = blockIdx.y;
    const int bm = blockIdx.x * MROWS;
    const int bn = c * 64;
    const int pool = c_pool[c];

    // ================= phase 1: proj (FFMA2, sequential K, chunk 32) =================
    {
        const int tr = tid >> 4;
        const int tc = tid & 15;

        ull acc[4][4];
#pragma unroll
        for (int p = 0; p < 4; ++p)
#pragma unroll
            for (int j = 0; j < 4; ++j) acc[p][j] = 0ull;

        const int lm = tid >> 1;              // X staging: row
        const int lk = (tid & 1) * 16;        // X staging: k offset (0 or 16)
        const int wk = tid >> 3;              // W staging: k (0..31)
        const int wn = (tid & 7) * 8;         // W staging: n offset

        for (int k0 = 0; k0 < D_MODEL_; k0 += KC) {
            const float* xrow = &X[(size_t)(bm + lm) * D_MODEL_ + k0 + lk];
#pragma unroll
            for (int s = 0; s < 4; ++s) {
                float4 xv = *reinterpret_cast<const float4*>(xrow + s * 4);
                As[(lk + s * 4 + 0) * 132 + lm] = xv.x;
                As[(lk + s * 4 + 1) * 132 + lm] = xv.y;
                As[(lk + s * 4 + 2) * 132 + lm] = xv.z;
                As[(lk + s * 4 + 3) * 132 + lm] = xv.w;
            }
            *reinterpret_cast<float4*>(&Bs[wk * 64 + wn]) =
                *reinterpret_cast<const float4*>(&W[(size_t)(k0 + wk) * PROJ_COLS + bn + wn]);
            *reinterpret_cast<float4*>(&Bs[wk * 64 + wn + 4]) =
                *reinterpret_cast<const float4*>(&W[(size_t)(k0 + wk) * PROJ_COLS + bn + wn + 4]);
            __syncthreads();
#pragma unroll
            for (int k = 0; k < KC; ++k) {
                const ull* ap = reinterpret_cast<const ull*>(&As[k * 132 + tr * 8]);
                ull a0 = ap[0], a1 = ap[1], a2 = ap[2], a3 = ap[3];
                float4 b = *reinterpret_cast<const float4*>(&Bs[k * 64 + tc * 4]);
                ull b0 = pack2(b.x, b.x), b1 = pack2(b.y, b.y);
                ull b2 = pack2(b.z, b.z), b3 = pack2(b.w, b.w);
                acc[0][0] = ffma2(a0, b0, acc[0][0]); acc[0][1] = ffma2(a0, b1, acc[0][1]);
                acc[0][2] = ffma2(a0, b2, acc[0][2]); acc[0][3] = ffma2(a0, b3, acc[0][3]);
                acc[1][0] = ffma2(a1, b0, acc[1][0]); acc[1][1] = ffma2(a1, b1, acc[1][1]);
                acc[1][2] = ffma2(a1, b2, acc[1][2]); acc[1][3] = ffma2(a1, b3, acc[1][3]);
                acc[2][0] = ffma2(a2, b0, acc[2][0]); acc[2][1] = ffma2(a2, b1, acc[2][1]);
                acc[2][2] = ffma2(a2, b2, acc[2][2]); acc[2][3] = ffma2(a2, b3, acc[2][3]);
                acc[3][0] = ffma2(a3, b0, acc[3][0]); acc[3][1] = ffma2(a3, b1, acc[3][1]);
                acc[3][2] = ffma2(a3, b2, acc[3][2]); acc[3][3] = ffma2(a3, b3, acc[3][3]);
            }
            __syncthreads();
        }

        float4 bb = *reinterpret_cast<const float4*>(bias + bn + tc * 4);
#pragma unroll
        for (int p = 0; p < 4; ++p) {
            float2 u0 = unpack2(acc[p][0]);
            float2 u1 = unpack2(acc[p][1]);
            float2 u2 = unpack2(acc[p][2]);
            float2 u3 = unpack2(acc[p][3]);
            int row = bm + tr * 8 + 2 * p;
            *reinterpret_cast<float4*>(&g_proj[(size_t)row * PROJ_COLS + bn + tc * 4]) =
                make_float4(u0.x + bb.x, u1.x + bb.y, u2.x + bb.z, u3.x + bb.w);
            *reinterpret_cast<float4*>(&g_proj[(size_t)(row + 1) * PROJ_COLS + bn + tc * 4]) =
                make_float4(u0.y + bb.x, u1.y + bb.y, u2.y + bb.z, u3.y + bb.w);
        }
    }
    __syncthreads();

    // ================= phase 2: coarse =================
    char* sB = smem;      // overlays As/Bs (dead after phase 1)

    const int rowA = bm + wid * 16 + (lane >> 2);
    const int rowB = rowA + 8;
    const float* p0 = g_proj + (size_t)rowA * PROJ_COLS + bn + (lane & 3) * 2;
    const float* p1 = g_proj + (size_t)rowB * PROJ_COLS + bn + (lane & 3) * 2;
    u32 a_hi[4][4];
#pragma unroll
    for (int ks = 0; ks < 4; ++ks) {
        float2 v00 = *reinterpret_cast<const float2*>(p0 + ks * 16);
        float2 v10 = *reinterpret_cast<const float2*>(p1 + ks * 16);
        float2 v01 = *reinterpret_cast<const float2*>(p0 + ks * 16 + 8);
        float2 v11 = *reinterpret_cast<const float2*>(p1 + ks * 16 + 8);
        a_hi[ks][0] = bf16x2_hi(v00.x, v00.y);
        a_hi[ks][1] = bf16x2_hi(v10.x, v10.y);
        a_hi[ks][2] = bf16x2_hi(v01.x, v01.y);
        a_hi[ks][3] = bf16x2_hi(v11.x, v11.y);
    }

    u32 keysA[TPAIR], keysB[TPAIR];
#pragma unroll
    for (int j = 0; j < TPAIR; ++j) { keysA[j] = 0u; keysB[j] = 0u; }
    float za = 0.f, zb = 0.f;

    const __nv_bfloat16* EH = g_ehi + (size_t)pool * N_POOL * D_SP;

#pragma unroll 1
    for (int t = 0; t < 8; ++t) {
        const uint4* sh = reinterpret_cast<const uint4*>(EH + (size_t)t * NTILE * D_SP);
#pragma unroll
        for (int j = 0; j < 8; ++j) {
            int u = tid + 256 * j;                  // uint4 index, 0..2047
            int nl = u >> 3, kq = u & 7;
            *reinterpret_cast<uint4*>(sB + nl * (EPAD * 2) + kq * 16) = sh[u];
        }
        __syncthreads();

#pragma unroll 1
        for (int jc = 0; jc < 4; ++jc) {
            float acc[8][4];
#pragma unroll
            for (int jn = 0; jn < 8; ++jn)
#pragma unroll
                for (int e = 0; e < 4; ++e) acc[jn][e] = 0.f;

#pragma unroll
            for (int ks = 0; ks < 4; ++ks) {
#pragma unroll
                for (int jn = 0; jn < 8; ++jn) {
                    int nl = jc * 64 + jn * 8 + (lane >> 2);
                    // permuted row: B-frag (b0,b1) for (ks, q) is 8B-adjacent
                    const char* bp = sB + nl * (EPAD * 2) + ks * 32 + (lane & 3) * 8;
                    uint2 bb = *reinterpret_cast<const uint2*>(bp);
                    mma16816(acc[jn], a_hi[ks], bb.x, bb.y);
                }
            }

            const u32 inv_pb = (u32)(255 - (t * 32 + jc * 8));   // 255 - pairidx base
#pragma unroll
            for (int jn = 0; jn < 8; ++jn) {
                const u32 inv_p = inv_pb - (u32)jn;
                float v0 = acc[jn][0], v1 = acc[jn][1];
                za += __expf(v0) + __expf(v1);
                u32 kA = make_key(fmaxf(v0, v1), inv_p);
                if (kA > keysA[TPAIR - 1]) {
#pragma unroll
                    for (int j = 0; j < TPAIR; ++j) {
                        u32 lo = umin(keysA[j], kA);
                        keysA[j] = umax(keysA[j], kA);
                        kA = lo;
                    }
                }
                float v2 = acc[jn][2], v3 = acc[jn][3];
                zb += __expf(v2) + __expf(v3);
                u32 kB = make_key(fmaxf(v2, v3), inv_p);
                if (kB > keysB[TPAIR - 1]) {
#pragma unroll
                    for (int j = 0; j < TPAIR; ++j) {
                        u32 lo = umin(keysB[j], kB);
                        keysB[j] = umax(keysB[j], kB);
                        kB = lo;
                    }
                }
            }
        }
        __syncthreads();
    }

    // ---- emit candidate base columns + Z partials ----
    const int q = lane & 3;
    const size_t taskA = (size_t)c * ROWS_TOT + rowA;
    const size_t taskB = (size_t)c * ROWS_TOT + rowB;
    u32* cA = g_cand + taskA * CAND_ROW + q * TPAIR;
    u32* cB = g_cand + taskB * CAND_ROW + q * TPAIR;
#pragma unroll
    for (int j = 0; j < TPAIR; ++j) {
        u32 pA = 255u - (keysA[j] & 0xFFu);
        u32 pB = 255u - (keysB[j] & 0xFFu);
        cA[j] = ((pA >> 5) << 8) + (((pA >> 3) & 3u) << 6) + ((pA & 7u) << 3) + q * 2;
        cB[j] = ((pB >> 5) << 8) + (((pB >> 3) & 3u) << 6) + ((pB & 7u) << 3) + q * 2;
    }
    g_z[taskA * 4 + q] = za;
    g_z[taskB * 4 + q] = zb;
}

// ---------------- kernel 3: refine — smem-staged exact fp32 dots + top-8 + scatter ----------------
// grid 6144, 256 threads = 8 warps, 1 warp per row-task. 64 candidates/row in 4 batches of 16.
#define ER_STRIDE 17        // float4 units per staged e-row (272B, conflict-free)
__global__ __launch_bounds__(256)
void k_refine(float* __restrict__ out) {
    __shared__ float sh_h[8][64];
    __shared__ u32   sh_c[8][CAND_ROW];
    __shared__ __align__(16) float4 sh_e[8][16 * ER_STRIDE];   // 4352 B per warp
    const int tid = threadIdx.x;
    const int wid = tid >> 5;
    const int lane = tid & 31;
    const size_t task = (size_t)blockIdx.x * 8 + wid;   // 0 .. 49151
    const int c = (int)(task >> 13);
    const int r = (int)(task & 8191);
    const int pool = c_pool[c];

    // stage h row (64 floats) + candidate pair bases (32 u32)
    if (lane < 16)
        *reinterpret_cast<float4*>(&sh_h[wid][lane * 4]) =
            *reinterpret_cast<const float4*>(&g_proj[(size_t)r * PROJ_COLS + c * 64 + lane * 4]);
    sh_c[wid][lane] = g_cand[task * CAND_ROW + lane];
    __syncwarp();

    const float* EP = g_enorm + (size_t)pool * N_POOL * D_SP;
    const float4* h4 = reinterpret_cast<const float4*>(sh_h[wid]);

    int   scol[2];
    float sval[2];
    bool  used[2];

#pragma unroll 1
    for (int b = 0; b < 4; ++b) {
        // ---- stage 8 pairs (16 candidates) = 8 x 512B contiguous ----
#pragma unroll
        for (int p8 = 0; p8 < 8; ++p8) {
            int base = (int)sh_c[wid][b * 8 + p8];           // even col; 512B block
            float4 v = reinterpret_cast<const float4*>(EP + (size_t)base * D_SP)[lane];
            int lrow = 2 * p8 + (lane >> 4);                 // local cand row 0..15
            sh_e[wid][lrow * ER_STRIDE + (lane & 15)] = v;
        }
        __syncwarp();

        // ---- 16 lanes compute their serial fp32 dot from smem ----
        const int half = b & 1;            // which 16-lane half is active
        const int k = b >> 1;              // register slot
        if ((lane >> 4) == half) {
            const int l15 = lane & 15;
            const int s = b * 16 + l15;    // global slot 0..63
            const float4* e4 = &sh_e[wid][l15 * ER_STRIDE];
            float a = 0.f;
#pragma unroll
            for (int i = 0; i < 16; ++i) {
                float4 e = e4[i], h = h4[i];
                a += h.x * e.x; a += h.y * e.y; a += h.z * e.z; a += h.w * e.w;
            }
            scol[k] = (int)sh_c[wid][s >> 1] + (s & 1);
            sval[k] = a;
            used[k] = false;
        }
        __syncwarp();   // done reading sh_e before next batch overwrites
    }

    float4 zp = *reinterpret_cast<const float4*>(&g_z[task * 4]);
    const float z = zp.x + zp.y + zp.z + zp.w;

    // 8 argmax rounds over 64 candidates, tie -> lower col; cols are distinct
    float rem0 = sval[0], rem1 = sval[1];
    float s8 = 0.f;
#pragma unroll 1
    for (int s = 0; s < 8; ++s) {
        float bv = rem0; int bi = scol[0];
        if (rem1 > bv || (rem1 == bv && scol[1] < bi)) { bv = rem1; bi = scol[1]; }
#pragma unroll
        for (int o = 16; o > 0; o >>= 1) {
            float ov = __shfl_xor_sync(0xffffffffu, bv, o);
            int   oi = __shfl_xor_sync(0xffffffffu, bi, o);
            if (ov > bv || (ov == bv && oi < bi)) { bv = ov; bi = oi; }
        }
        s8 += __expf(bv);
        if (bi == scol[0] && !used[0]) { used[0] = true; rem0 = -FLT_MAX; }
        else if (bi == scol[1] && !used[1]) { used[1] = true; rem1 = -FLT_MAX; }
    }
    const float inv = 1.0f / (s8 + 1e-8f * z);

    // zero row, then scatter refined values for selected slots
    float* orow = out + task * (size_t)N_POOL;
    float4* o4 = reinterpret_cast<float4*>(orow);
    const float4 zz = make_float4(0.f, 0.f, 0.f, 0.f);
#pragma unroll
    for (int i = 0; i < 16; ++i) o4[lane + 32 * i] = zz;
    __syncwarp();
    if (used[0]) orow[scol[0]] = __expf(sval[0]) * inv;
    if (used[1]) orow[scol[1]] = __expf(sval[1]) * inv;
}

// ---------------- launch ----------------
extern "C" void kernel_launch(void* const* d_in, const int* in_sizes, int n_in,
                              void* d_out, int out_size) {
    (void)in_sizes; (void)n_in; (void)out_size;
    const float* x   = (const float*)d_in[0];   // (4,2048,1024)
    const float* W   = (const float*)d_in[1];   // (1024,384)
    const float* b   = (const float*)d_in[2];   // (384,)
    const float* emb = (const float*)d_in[3];   // (10240,64)
    float* out = (float*)d_out;                 // (6,4,2048,2048)

    k_pre<<<1, 1>>>();
    k_norm<<<128, 256>>>(emb);
    k_pc<<<dim3(ROWS_TOT / MROWS, 6), 256, SMEM_BYTES>>>(x, W, b);
    k_refine<<<6 * ROWS_TOT / 8, 256>>>(out);
}

// round 15
// speedup vs baseline: 1.0092x; 1.0092x over previous
#include <cuda_runtime.h>
#include <cuda_bf16.h>
#include <math.h>
#include <float.h>

typedef unsigned long long ull;
typedef unsigned int u32;

#define N_POOL   2048
#define D_SP     64
#define ROWS_TOT 8192
#define D_MODEL_ 1024
#define PROJ_COLS 384
#define TPAIR    8           // pairs kept per quad-lane (provably sufficient)
#define CAND_ROW 32          // 4 lanes * TPAIR pair entries per row
#define LOG2E    1.4426950408889634f

// ---------------- scratch ----------------
__device__ float g_proj[ROWS_TOT * PROJ_COLS];                       // 12.6 MB
__device__ __align__(128) __nv_bfloat16 g_ehi[4 * N_POOL * D_SP];    // 1 MB  bf16 [n][64] (MMA-frag permuted)
__device__ __align__(128) float g_enorm[4 * N_POOL * D_SP];          // 2 MB  fp32 [n][64] (original order)
__device__ u32   g_cand[6 * ROWS_TOT * CAND_ROW];                    // 6.3 MB (pair base cols)
__device__ float g_z[6 * ROWS_TOT * 4];                              // 0.8 MB

__constant__ int c_pool[6] = {0, 0, 1, 2, 2, 3};

// ---------------- f32x2 helpers (proj phase) ----------------
__device__ __forceinline__ ull pack2(float lo, float hi) {
    ull u; asm("mov.b64 %0, {%1, %2};" : "=l"(u) : "f"(lo), "f"(hi)); return u;
}
__device__ __forceinline__ float2 unpack2(ull u) {
    float2 v; asm("mov.b64 {%0, %1}, %2;" : "=f"(v.x), "=f"(v.y) : "l"(u)); return v;
}
__device__ __forceinline__ ull ffma2(ull a, ull b, ull c) {
    ull d; asm("fma.rn.f32x2 %0, %1, %2, %3;" : "=l"(d) : "l"(a), "l"(b), "l"(c)); return d;
}

// ---------------- mma.sync m16n8k16 bf16 (HMMA fallback on sm_103) ----------------
__device__ __forceinline__ void mma16816(float (&d)[4], const u32 (&a)[4], u32 b0, u32 b1) {
    asm volatile(
        "mma.sync.aligned.m16n8k16.row.col.f32.bf16.bf16.f32 "
        "{%0,%1,%2,%3}, {%4,%5,%6,%7}, {%8,%9}, {%0,%1,%2,%3};"
        : "+f"(d[0]), "+f"(d[1]), "+f"(d[2]), "+f"(d[3])
        : "r"(a[0]), "r"(a[1]), "r"(a[2]), "r"(a[3]), "r"(b0), "r"(b1));
}

// ---------------- bf16 / math helpers ----------------
__device__ __forceinline__ u32 bf16x2_hi(float x, float y) {
    __nv_bfloat16 hx = __float2bfloat16(x), hy = __float2bfloat16(y);
    return (u32)__bfloat16_as_ushort(hx) | ((u32)__bfloat16_as_ushort(hy) << 16);
}
__device__ __forceinline__ float ex2f(float x) {
    float y; asm("ex2.approx.f32 %0, %1;" : "=f"(y) : "f"(x)); return y;
}

// ---------------- dummy kernel (ncu slot control: profiled launch = #4) ----------------
__global__ void k_pre() {}

// ---------------- kernel 1: normalize emb rows -> fp32 (orig order) + bf16 (frag-permuted) ----------------
// bf16 permutation within each 64-elem row: old k = ks*16 + h*8 + q*2 + e  ->
// new kp = ks*16 + q*4 + h*2 + e, so each MMA B-fragment (b0,b1 for fixed ks,q) is 8B-adjacent.
__global__ __launch_bounds__(256) void k_norm(const float* __restrict__ emb) {
    const int tid = threadIdx.x;
    const int n = blockIdx.x * 64 + (tid >> 2);      // neuron 0..8191
    const int q16 = (tid & 3) * 16;
    const float* r = emb + (size_t)n * D_SP + q16;
    float v[16]; float ss = 0.f;
#pragma unroll
    for (int i = 0; i < 16; ++i) { v[i] = r[i]; ss += v[i] * v[i]; }
    ss += __shfl_xor_sync(0xffffffffu, ss, 1);
    ss += __shfl_xor_sync(0xffffffffu, ss, 2);
    const float nrm = fmaxf(sqrtf(ss), 1e-12f);
    float* of = g_enorm + (size_t)n * D_SP + q16;
    __nv_bfloat16* ohb = g_ehi + (size_t)n * D_SP;
#pragma unroll
    for (int i = 0; i < 16; ++i) {
        float x = v[i] / nrm;
        of[i] = x;
        int k = q16 + i;
        int ks = k >> 4, rr = k & 15;
        int h = (rr >> 3) & 1, qq = (rr >> 1) & 3, e = k & 1;
        ohb[ks * 16 + qq * 4 + h * 2 + e] = __float2bfloat16(x);
    }
}

// ---------------- fused kernel: proj (FFMA2, exact) + coarse (bf16 MMA) ----------------
// grid (64, 6), 256 threads. blockIdx.x = 128-row tile, blockIdx.y = chunk c.
#define MROWS 128
#define NTILE 256
#define EPAD  72            // bf16 elements per padded row (144 B)
#define KC    32            // proj K-chunk
#define SMEM_BYTES (NTILE * EPAD * 2)   // 36864; >= proj phase's 16896+8192

__global__ __launch_bounds__(256, 2)
void k_pc(const float* __restrict__ X, const float* __restrict__ W,
          const float* __restrict__ bias) {
    extern __shared__ __align__(16) char smem[];
    float* As = reinterpret_cast<float*>(smem);               // [32][132] = 16896 B
    float* Bs = reinterpret_cast<float*>(smem) + 32 * 132;    // [32][64]  =  8192 B

    const int tid = threadIdx.x;
    const int wid = tid >> 5;
    const int lane = tid & 31;
    const int c = blockIdx.y;
    const int bm = blockIdx.x * MROWS;
    const int bn = c * 64;
    const int pool = c_pool[c];

    // ================= phase 1: proj (FFMA2, sequential K, chunk 32) =================
    {
        const int tr = tid >> 4;
        const int tc = tid & 15;

        ull acc[4][4];
#pragma unroll
        for (int p = 0; p < 4; ++p)
#pragma unroll
            for (int j = 0; j < 4; ++j) acc[p][j] = 0ull;

        const int lm = tid >> 1;              // X staging: row
        const int lk = (tid & 1) * 16;        // X staging: k offset (0 or 16)
        const int wk = tid >> 3;              // W staging: k (0..31)
        const int wn = (tid & 7) * 8;         // W staging: n offset

        for (int k0 = 0; k0 < D_MODEL_; k0 += KC) {
            const float* xrow = &X[(size_t)(bm + lm) * D_MODEL_ + k0 + lk];
#pragma unroll
            for (int s = 0; s < 4; ++s) {
                float4 xv = *reinterpret_cast<const float4*>(xrow + s * 4);
                As[(lk + s * 4 + 0) * 132 + lm] = xv.x;
                As[(lk + s * 4 + 1) * 132 + lm] = xv.y;
                As[(lk + s * 4 + 2) * 132 + lm] = xv.z;
                As[(lk + s * 4 + 3) * 132 + lm] = xv.w;
            }
            *reinterpret_cast<float4*>(&Bs[wk * 64 + wn]) =
                *reinterpret_cast<const float4*>(&W[(size_t)(k0 + wk) * PROJ_COLS + bn + wn]);
            *reinterpret_cast<float4*>(&Bs[wk * 64 + wn + 4]) =
                *reinterpret_cast<const float4*>(&W[(size_t)(k0 + wk) * PROJ_COLS + bn + wn + 4]);
            __syncthreads();
#pragma unroll
            for (int k = 0; k < KC; ++k) {
                const ull* ap = reinterpret_cast<const ull*>(&As[k * 132 + tr * 8]);
                ull a0 = ap[0], a1 = ap[1], a2 = ap[2], a3 = ap[3];
                float4 b = *reinterpret_cast<const float4*>(&Bs[k * 64 + tc * 4]);
                ull b0 = pack2(b.x, b.x), b1 = pack2(b.y, b.y);
                ull b2 = pack2(b.z, b.z), b3 = pack2(b.w, b.w);
                acc[0][0] = ffma2(a0, b0, acc[0][0]); acc[0][1] = ffma2(a0, b1, acc[0][1]);
                acc[0][2] = ffma2(a0, b2, acc[0][2]); acc[0][3] = ffma2(a0, b3, acc[0][3]);
                acc[1][0] = ffma2(a1, b0, acc[1][0]); acc[1][1] = ffma2(a1, b1, acc[1][1]);
                acc[1][2] = ffma2(a1, b2, acc[1][2]); acc[1][3] = ffma2(a1, b3, acc[1][3]);
                acc[2][0] = ffma2(a2, b0, acc[2][0]); acc[2][1] = ffma2(a2, b1, acc[2][1]);
                acc[2][2] = ffma2(a2, b2, acc[2][2]); acc[2][3] = ffma2(a2, b3, acc[2][3]);
                acc[3][0] = ffma2(a3, b0, acc[3][0]); acc[3][1] = ffma2(a3, b1, acc[3][1]);
                acc[3][2] = ffma2(a3, b2, acc[3][2]); acc[3][3] = ffma2(a3, b3, acc[3][3]);
            }
            __syncthreads();
        }

        float4 bb = *reinterpret_cast<const float4*>(bias + bn + tc * 4);
#pragma unroll
        for (int p = 0; p < 4; ++p) {
            float2 u0 = unpack2(acc[p][0]);
            float2 u1 = unpack2(acc[p][1]);
            float2 u2 = unpack2(acc[p][2]);
            float2 u3 = unpack2(acc[p][3]);
            int row = bm + tr * 8 + 2 * p;
            *reinterpret_cast<float4*>(&g_proj[(size_t)row * PROJ_COLS + bn + tc * 4]) =
                make_float4(u0.x + bb.x, u1.x + bb.y, u2.x + bb.z, u3.x + bb.w);
            *reinterpret_cast<float4*>(&g_proj[(size_t)(row + 1) * PROJ_COLS + bn + tc * 4]) =
                make_float4(u0.y + bb.x, u1.y + bb.y, u2.y + bb.z, u3.y + bb.w);
        }
    }
    __syncthreads();

    // ================= phase 2: coarse =================
    char* sB = smem;      // overlays As/Bs (dead after phase 1)

    // A fragments prescaled by log2(e): MMA acc = logit*log2e, so exp(v) = EX2(acc).
    const int rowA = bm + wid * 16 + (lane >> 2);
    const int rowB = rowA + 8;
    const float* p0 = g_proj + (size_t)rowA * PROJ_COLS + bn + (lane & 3) * 2;
    const float* p1 = g_proj + (size_t)rowB * PROJ_COLS + bn + (lane & 3) * 2;
    u32 a_hi[4][4];
#pragma unroll
    for (int ks = 0; ks < 4; ++ks) {
        float2 v00 = *reinterpret_cast<const float2*>(p0 + ks * 16);
        float2 v10 = *reinterpret_cast<const float2*>(p1 + ks * 16);
        float2 v01 = *reinterpret_cast<const float2*>(p0 + ks * 16 + 8);
        float2 v11 = *reinterpret_cast<const float2*>(p1 + ks * 16 + 8);
        a_hi[ks][0] = bf16x2_hi(v00.x * LOG2E, v00.y * LOG2E);
        a_hi[ks][1] = bf16x2_hi(v10.x * LOG2E, v10.y * LOG2E);
        a_hi[ks][2] = bf16x2_hi(v01.x * LOG2E, v01.y * LOG2E);
        a_hi[ks][3] = bf16x2_hi(v11.x * LOG2E, v11.y * LOG2E);
    }

    u32 keysA[TPAIR], keysB[TPAIR];
#pragma unroll
    for (int j = 0; j < TPAIR; ++j) { keysA[j] = 0u; keysB[j] = 0u; }
    float za = 0.f, zb = 0.f;

    const __nv_bfloat16* EH = g_ehi + (size_t)pool * N_POOL * D_SP;

#pragma unroll 1
    for (int t = 0; t < 8; ++t) {
        const uint4* sh = reinterpret_cast<const uint4*>(EH + (size_t)t * NTILE * D_SP);
#pragma unroll
        for (int j = 0; j < 8; ++j) {
            int u = tid + 256 * j;                  // uint4 index, 0..2047
            int nl = u >> 3, kq = u & 7;
            *reinterpret_cast<uint4*>(sB + nl * (EPAD * 2) + kq * 16) = sh[u];
        }
        __syncthreads();

#pragma unroll 1
        for (int jc = 0; jc < 4; ++jc) {
            float acc[8][4];
#pragma unroll
            for (int jn = 0; jn < 8; ++jn)
#pragma unroll
                for (int e = 0; e < 4; ++e) acc[jn][e] = 0.f;

#pragma unroll
            for (int ks = 0; ks < 4; ++ks) {
#pragma unroll
                for (int jn = 0; jn < 8; ++jn) {
                    int nl = jc * 64 + jn * 8 + (lane >> 2);
                    // permuted row: B-frag (b0,b1) for (ks, q) is 8B-adjacent
                    const char* bp = sB + nl * (EPAD * 2) + ks * 32 + (lane & 3) * 8;
                    uint2 bb = *reinterpret_cast<const uint2*>(bp);
                    mma16816(acc[jn], a_hi[ks], bb.x, bb.y);
                }
            }

            const u32 inv_pb = (u32)(255 - (t * 32 + jc * 8));   // 255 - pairidx base
#pragma unroll
            for (int jn = 0; jn < 8; ++jn) {
                const u32 inv_p = inv_pb - (u32)jn;
                // row A pair: exp via direct EX2; positive floats are uint-ordered
                float ez0 = ex2f(acc[jn][0]), ez1 = ex2f(acc[jn][1]);
                za += ez0 + ez1;
                u32 kA = (__float_as_uint(fmaxf(ez0, ez1)) & 0xFFFFFF00u) | inv_p;
                if (kA > keysA[TPAIR - 1]) {
#pragma unroll
                    for (int j = 0; j < TPAIR; ++j) {
                        u32 lo = umin(keysA[j], kA);
                        keysA[j] = umax(keysA[j], kA);
                        kA = lo;
                    }
                }
                // row B pair
                float ez2 = ex2f(acc[jn][2]), ez3 = ex2f(acc[jn][3]);
                zb += ez2 + ez3;
                u32 kB = (__float_as_uint(fmaxf(ez2, ez3)) & 0xFFFFFF00u) | inv_p;
                if (kB > keysB[TPAIR - 1]) {
#pragma unroll
                    for (int j = 0; j < TPAIR; ++j) {
                        u32 lo = umin(keysB[j], kB);
                        keysB[j] = umax(keysB[j], kB);
                        kB = lo;
                    }
                }
            }
        }
        __syncthreads();
    }

    // ---- emit candidate base columns + Z partials ----
    const int q = lane & 3;
    const size_t taskA = (size_t)c * ROWS_TOT + rowA;
    const size_t taskB = (size_t)c * ROWS_TOT + rowB;
    u32* cA = g_cand + taskA * CAND_ROW + q * TPAIR;
    u32* cB = g_cand + taskB * CAND_ROW + q * TPAIR;
#pragma unroll
    for (int j = 0; j < TPAIR; ++j) {
        u32 pA = 255u - (keysA[j] & 0xFFu);
        u32 pB = 255u - (keysB[j] & 0xFFu);
        cA[j] = ((pA >> 5) << 8) + (((pA >> 3) & 3u) << 6) + ((pA & 7u) << 3) + q * 2;
        cB[j] = ((pB >> 5) << 8) + (((pB >> 3) & 3u) << 6) + ((pB & 7u) << 3) + q * 2;
    }
    g_z[taskA * 4 + q] = za;
    g_z[taskB * 4 + q] = zb;
}

// ---------------- kernel 3: refine — smem-staged exact fp32 dots + top-8 + scatter ----------------
// grid 6144, 256 threads = 8 warps, 1 warp per row-task. 64 candidates/row in 4 batches of 16.
#define ER_STRIDE 17        // float4 units per staged e-row (272B, conflict-free)
__global__ __launch_bounds__(256)
void k_refine(float* __restrict__ out) {
    __shared__ float sh_h[8][64];
    __shared__ u32   sh_c[8][CAND_ROW];
    __shared__ __align__(16) float4 sh_e[8][16 * ER_STRIDE];   // 4352 B per warp
    const int tid = threadIdx.x;
    const int wid = tid >> 5;
    const int lane = tid & 31;
    const size_t task = (size_t)blockIdx.x * 8 + wid;   // 0 .. 49151
    const int c = (int)(task >> 13);
    const int r = (int)(task & 8191);
    const int pool = c_pool[c];

    // stage h row (64 floats) + candidate pair bases (32 u32)
    if (lane < 16)
        *reinterpret_cast<float4*>(&sh_h[wid][lane * 4]) =
            *reinterpret_cast<const float4*>(&g_proj[(size_t)r * PROJ_COLS + c * 64 + lane * 4]);
    sh_c[wid][lane] = g_cand[task * CAND_ROW + lane];
    __syncwarp();

    const float* EP = g_enorm + (size_t)pool * N_POOL * D_SP;
    const float4* h4 = reinterpret_cast<const float4*>(sh_h[wid]);

    int   scol[2];
    float sval[2];
    bool  used[2];

#pragma unroll 1
    for (int b = 0; b < 4; ++b) {
        // ---- stage 8 pairs (16 candidates) = 8 x 512B contiguous ----
#pragma unroll
        for (int p8 = 0; p8 < 8; ++p8) {
            int base = (int)sh_c[wid][b * 8 + p8];           // even col; 512B block
            float4 v = reinterpret_cast<const float4*>(EP + (size_t)base * D_SP)[lane];
            int lrow = 2 * p8 + (lane >> 4);                 // local cand row 0..15
            sh_e[wid][lrow * ER_STRIDE + (lane & 15)] = v;
        }
        __syncwarp();

        // ---- 16 lanes compute their serial fp32 dot from smem ----
        const int half = b & 1;            // which 16-lane half is active
        const int k = b >> 1;              // register slot
        if ((lane >> 4) == half) {
            const int l15 = lane & 15;
            const int s = b * 16 + l15;    // global slot 0..63
            const float4* e4 = &sh_e[wid][l15 * ER_STRIDE];
            float a = 0.f;
#pragma unroll
            for (int i = 0; i < 16; ++i) {
                float4 e = e4[i], h = h4[i];
                a += h.x * e.x; a += h.y * e.y; a += h.z * e.z; a += h.w * e.w;
            }
            scol[k] = (int)sh_c[wid][s >> 1] + (s & 1);
            sval[k] = a;
            used[k] = false;
        }
        __syncwarp();   // done reading sh_e before next batch overwrites
    }

    float4 zp = *reinterpret_cast<const float4*>(&g_z[task * 4]);
    const float z = zp.x + zp.y + zp.z + zp.w;

    // 8 argmax rounds over 64 candidates, tie -> lower col; cols are distinct
    float rem0 = sval[0], rem1 = sval[1];
    float s8 = 0.f;
#pragma unroll 1
    for (int s = 0; s < 8; ++s) {
        float bv = rem0; int bi = scol[0];
        if (rem1 > bv || (rem1 == bv && scol[1] < bi)) { bv = rem1; bi = scol[1]; }
#pragma unroll
        for (int o = 16; o > 0; o >>= 1) {
            float ov = __shfl_xor_sync(0xffffffffu, bv, o);
            int   oi = __shfl_xor_sync(0xffffffffu, bi, o);
            if (ov > bv || (ov == bv && oi < bi)) { bv = ov; bi = oi; }
        }
        s8 += __expf(bv);
        if (bi == scol[0] && !used[0]) { used[0] = true; rem0 = -FLT_MAX; }
        else if (bi == scol[1] && !used[1]) { used[1] = true; rem1 = -FLT_MAX; }
    }
    const float inv = 1.0f / (s8 + 1e-8f * z);

    // zero row, then scatter refined values for selected slots
    float* orow = out + task * (size_t)N_POOL;
    float4* o4 = reinterpret_cast<float4*>(orow);
    const float4 zz = make_float4(0.f, 0.f, 0.f, 0.f);
#pragma unroll
    for (int i = 0; i < 16; ++i) o4[lane + 32 * i] = zz;
    __syncwarp();
    if (used[0]) orow[scol[0]] = __expf(sval[0]) * inv;
    if (used[1]) orow[scol[1]] = __expf(sval[1]) * inv;
}

// ---------------- launch (k_pc deliberately placed as launch #4 for ncu) ----------------
extern "C" void kernel_launch(void* const* d_in, const int* in_sizes, int n_in,
                              void* d_out, int out_size) {
    (void)in_sizes; (void)n_in; (void)out_size;
    const float* x   = (const float*)d_in[0];   // (4,2048,1024)
    const float* W   = (const float*)d_in[1];   // (1024,384)
    const float* b   = (const float*)d_in[2];   // (384,)
    const float* emb = (const float*)d_in[3];   // (10240,64)
    float* out = (float*)d_out;                 // (6,4,2048,2048)

    k_pre<<<1, 1>>>();                                           // launch 1
    k_norm<<<128, 256>>>(emb);                                   // launch 2
    k_pre<<<1, 1>>>();                                           // launch 3 (slot shim)
    k_pc<<<dim3(ROWS_TOT / MROWS, 6), 256, SMEM_BYTES>>>(x, W, b); // launch 4 -> profiled
    k_refine<<<6 * ROWS_TOT / 8, 256>>>(out);                    // launch 5
}

// round 16
// speedup vs baseline: 1.0470x; 1.0374x over previous
#include <cuda_runtime.h>
#include <cuda_bf16.h>
#include <math.h>
#include <float.h>

typedef unsigned long long ull;
typedef unsigned int u32;

#define N_POOL   2048
#define D_SP     64
#define ROWS_TOT 8192
#define D_MODEL_ 1024
#define PROJ_COLS 384
#define TPAIR    8           // pairs kept per quad-lane (provably sufficient)
#define CAND_ROW 32          // 4 lanes * TPAIR pair entries per row
#define LOG2E    1.4426950408889634f

// ---------------- scratch ----------------
__device__ float g_proj[ROWS_TOT * PROJ_COLS];                       // 12.6 MB
__device__ __align__(128) __nv_bfloat16 g_ehi[4 * N_POOL * D_SP];    // 1 MB  bf16 [n][64] (MMA-frag permuted)
__device__ __align__(128) float g_enorm[4 * N_POOL * D_SP];          // 2 MB  fp32 [n][64] (original order)
__device__ u32   g_cand[6 * ROWS_TOT * CAND_ROW];                    // 6.3 MB (pair base cols)
__device__ float g_z[6 * ROWS_TOT * 4];                              // 0.8 MB

__constant__ int c_pool[6] = {0, 0, 1, 2, 2, 3};

// ---------------- f32x2 helpers (proj phase) ----------------
__device__ __forceinline__ ull pack2(float lo, float hi) {
    ull u; asm("mov.b64 %0, {%1, %2};" : "=l"(u) : "f"(lo), "f"(hi)); return u;
}
__device__ __forceinline__ float2 unpack2(ull u) {
    float2 v; asm("mov.b64 {%0, %1}, %2;" : "=f"(v.x), "=f"(v.y) : "l"(u)); return v;
}
__device__ __forceinline__ ull ffma2(ull a, ull b, ull c) {
    ull d; asm("fma.rn.f32x2 %0, %1, %2, %3;" : "=l"(d) : "l"(a), "l"(b), "l"(c)); return d;
}

// ---------------- mma.sync m16n8k16 bf16 (HMMA fallback on sm_103) ----------------
__device__ __forceinline__ void mma16816(float (&d)[4], const u32 (&a)[4], u32 b0, u32 b1) {
    asm volatile(
        "mma.sync.aligned.m16n8k16.row.col.f32.bf16.bf16.f32 "
        "{%0,%1,%2,%3}, {%4,%5,%6,%7}, {%8,%9}, {%0,%1,%2,%3};"
        : "+f"(d[0]), "+f"(d[1]), "+f"(d[2]), "+f"(d[3])
        : "r"(a[0]), "r"(a[1]), "r"(a[2]), "r"(a[3]), "r"(b0), "r"(b1));
}

// ---------------- bf16 / math helpers ----------------
__device__ __forceinline__ u32 bf16x2_hi(float x, float y) {
    __nv_bfloat16 hx = __float2bfloat16(x), hy = __float2bfloat16(y);
    return (u32)__bfloat16_as_ushort(hx) | ((u32)__bfloat16_as_ushort(hy) << 16);
}
__device__ __forceinline__ float ex2f(float x) {
    float y; asm("ex2.approx.f32 %0, %1;" : "=f"(y) : "f"(x)); return y;
}

// ---------------- dummy kernel (ncu slot control: profiled launch = #4) ----------------
__global__ void k_pre() {}

// ---------------- kernel 1: normalize emb rows -> fp32 (orig order) + bf16 (frag-permuted) ----------------
__global__ __launch_bounds__(256) void k_norm(const float* __restrict__ emb) {
    const int tid = threadIdx.x;
    const int n = blockIdx.x * 64 + (tid >> 2);      // neuron 0..8191
    const int q16 = (tid & 3) * 16;
    const float* r = emb + (size_t)n * D_SP + q16;
    float v[16]; float ss = 0.f;
#pragma unroll
    for (int i = 0; i < 16; ++i) { v[i] = r[i]; ss += v[i] * v[i]; }
    ss += __shfl_xor_sync(0xffffffffu, ss, 1);
    ss += __shfl_xor_sync(0xffffffffu, ss, 2);
    const float nrm = fmaxf(sqrtf(ss), 1e-12f);
    float* of = g_enorm + (size_t)n * D_SP + q16;
    __nv_bfloat16* ohb = g_ehi + (size_t)n * D_SP;
#pragma unroll
    for (int i = 0; i < 16; ++i) {
        float x = v[i] / nrm;
        of[i] = x;
        int k = q16 + i;
        int ks = k >> 4, rr = k & 15;
        int h = (rr >> 3) & 1, qq = (rr >> 1) & 3, e = k & 1;
        ohb[ks * 16 + qq * 4 + h * 2 + e] = __float2bfloat16(x);
    }
}

// ---------------- fused kernel: proj (FFMA2, exact) + coarse (bf16 MMA) ----------------
// grid (64, 6), 256 threads. Register double-buffered staging in both phases.
#define MROWS 128
#define NTILE 256
#define EPAD  72            // bf16 elements per padded row (144 B)
#define KC    32            // proj K-chunk
#define SMEM_BYTES (NTILE * EPAD * 2)   // 36864; >= proj phase's 16896+8192

__global__ __launch_bounds__(256, 2)
void k_pc(const float* __restrict__ X, const float* __restrict__ W,
          const float* __restrict__ bias) {
    extern __shared__ __align__(16) char smem[];
    float* As = reinterpret_cast<float*>(smem);               // [32][132] = 16896 B
    float* Bs = reinterpret_cast<float*>(smem) + 32 * 132;    // [32][64]  =  8192 B

    const int tid = threadIdx.x;
    const int wid = tid >> 5;
    const int lane = tid & 31;
    const int c = blockIdx.y;
    const int bm = blockIdx.x * MROWS;
    const int bn = c * 64;
    const int pool = c_pool[c];

    // ================= phase 1: proj (FFMA2, sequential K, chunk 32) =================
    {
        const int tr = tid >> 4;
        const int tc = tid & 15;

        ull acc[4][4];
#pragma unroll
        for (int p = 0; p < 4; ++p)
#pragma unroll
            for (int j = 0; j < 4; ++j) acc[p][j] = 0ull;

        const int lm = tid >> 1;              // X staging: row
        const int lk = (tid & 1) * 16;        // X staging: k offset (0 or 16)
        const int wk = tid >> 3;              // W staging: k (0..31)
        const int wn = (tid & 7) * 8;         // W staging: n offset

        // prefetch chunk 0 into registers
        float4 xr[4];
        float4 wr[2];
        {
            const float* xrow = &X[(size_t)(bm + lm) * D_MODEL_ + lk];
#pragma unroll
            for (int s = 0; s < 4; ++s)
                xr[s] = *reinterpret_cast<const float4*>(xrow + s * 4);
            wr[0] = *reinterpret_cast<const float4*>(&W[(size_t)wk * PROJ_COLS + bn + wn]);
            wr[1] = *reinterpret_cast<const float4*>(&W[(size_t)wk * PROJ_COLS + bn + wn + 4]);
        }

        for (int k0 = 0; k0 < D_MODEL_; k0 += KC) {
            // store prefetched registers to smem
#pragma unroll
            for (int s = 0; s < 4; ++s) {
                As[(lk + s * 4 + 0) * 132 + lm] = xr[s].x;
                As[(lk + s * 4 + 1) * 132 + lm] = xr[s].y;
                As[(lk + s * 4 + 2) * 132 + lm] = xr[s].z;
                As[(lk + s * 4 + 3) * 132 + lm] = xr[s].w;
            }
            *reinterpret_cast<float4*>(&Bs[wk * 64 + wn]) = wr[0];
            *reinterpret_cast<float4*>(&Bs[wk * 64 + wn + 4]) = wr[1];
            __syncthreads();

            // prefetch next chunk (LDG latency hidden behind compute below)
            if (k0 + KC < D_MODEL_) {
                const float* xrow = &X[(size_t)(bm + lm) * D_MODEL_ + k0 + KC + lk];
#pragma unroll
                for (int s = 0; s < 4; ++s)
                    xr[s] = *reinterpret_cast<const float4*>(xrow + s * 4);
                wr[0] = *reinterpret_cast<const float4*>(&W[(size_t)(k0 + KC + wk) * PROJ_COLS + bn + wn]);
                wr[1] = *reinterpret_cast<const float4*>(&W[(size_t)(k0 + KC + wk) * PROJ_COLS + bn + wn + 4]);
            }

#pragma unroll
            for (int k = 0; k < KC; ++k) {
                const ull* ap = reinterpret_cast<const ull*>(&As[k * 132 + tr * 8]);
                ull a0 = ap[0], a1 = ap[1], a2 = ap[2], a3 = ap[3];
                float4 b = *reinterpret_cast<const float4*>(&Bs[k * 64 + tc * 4]);
                ull b0 = pack2(b.x, b.x), b1 = pack2(b.y, b.y);
                ull b2 = pack2(b.z, b.z), b3 = pack2(b.w, b.w);
                acc[0][0] = ffma2(a0, b0, acc[0][0]); acc[0][1] = ffma2(a0, b1, acc[0][1]);
                acc[0][2] = ffma2(a0, b2, acc[0][2]); acc[0][3] = ffma2(a0, b3, acc[0][3]);
                acc[1][0] = ffma2(a1, b0, acc[1][0]); acc[1][1] = ffma2(a1, b1, acc[1][1]);
                acc[1][2] = ffma2(a1, b2, acc[1][2]); acc[1][3] = ffma2(a1, b3, acc[1][3]);
                acc[2][0] = ffma2(a2, b0, acc[2][0]); acc[2][1] = ffma2(a2, b1, acc[2][1]);
                acc[2][2] = ffma2(a2, b2, acc[2][2]); acc[2][3] = ffma2(a2, b3, acc[2][3]);
                acc[3][0] = ffma2(a3, b0, acc[3][0]); acc[3][1] = ffma2(a3, b1, acc[3][1]);
                acc[3][2] = ffma2(a3, b2, acc[3][2]); acc[3][3] = ffma2(a3, b3, acc[3][3]);
            }
            __syncthreads();
        }

        float4 bb = *reinterpret_cast<const float4*>(bias + bn + tc * 4);
#pragma unroll
        for (int p = 0; p < 4; ++p) {
            float2 u0 = unpack2(acc[p][0]);
            float2 u1 = unpack2(acc[p][1]);
            float2 u2 = unpack2(acc[p][2]);
            float2 u3 = unpack2(acc[p][3]);
            int row = bm + tr * 8 + 2 * p;
            *reinterpret_cast<float4*>(&g_proj[(size_t)row * PROJ_COLS + bn + tc * 4]) =
                make_float4(u0.x + bb.x, u1.x + bb.y, u2.x + bb.z, u3.x + bb.w);
            *reinterpret_cast<float4*>(&g_proj[(size_t)(row + 1) * PROJ_COLS + bn + tc * 4]) =
                make_float4(u0.y + bb.x, u1.y + bb.y, u2.y + bb.z, u3.y + bb.w);
        }
    }
    __syncthreads();

    // ================= phase 2: coarse =================
    char* sB = smem;      // overlays As/Bs (dead after phase 1)

    // A fragments prescaled by log2(e): MMA acc = logit*log2e, so exp(v) = EX2(acc).
    const int rowA = bm + wid * 16 + (lane >> 2);
    const int rowB = rowA + 8;
    const float* p0 = g_proj + (size_t)rowA * PROJ_COLS + bn + (lane & 3) * 2;
    const float* p1 = g_proj + (size_t)rowB * PROJ_COLS + bn + (lane & 3) * 2;
    u32 a_hi[4][4];
#pragma unroll
    for (int ks = 0; ks < 4; ++ks) {
        float2 v00 = *reinterpret_cast<const float2*>(p0 + ks * 16);
        float2 v10 = *reinterpret_cast<const float2*>(p1 + ks * 16);
        float2 v01 = *reinterpret_cast<const float2*>(p0 + ks * 16 + 8);
        float2 v11 = *reinterpret_cast<const float2*>(p1 + ks * 16 + 8);
        a_hi[ks][0] = bf16x2_hi(v00.x * LOG2E, v00.y * LOG2E);
        a_hi[ks][1] = bf16x2_hi(v10.x * LOG2E, v10.y * LOG2E);
        a_hi[ks][2] = bf16x2_hi(v01.x * LOG2E, v01.y * LOG2E);
        a_hi[ks][3] = bf16x2_hi(v11.x * LOG2E, v11.y * LOG2E);
    }

    u32 keysA[TPAIR], keysB[TPAIR];
#pragma unroll
    for (int j = 0; j < TPAIR; ++j) { keysA[j] = 0u; keysB[j] = 0u; }
    float za = 0.f, zb = 0.f;

    const __nv_bfloat16* EH = g_ehi + (size_t)pool * N_POOL * D_SP;

    // prefetch tile 0 (4 uint4 per thread; second half loaded in-loop to cap regs)
    uint4 er[4];
    {
        const uint4* sh = reinterpret_cast<const uint4*>(EH);
#pragma unroll
        for (int j = 0; j < 4; ++j) er[j] = sh[tid + 256 * j];
    }

#pragma unroll 1
    for (int t = 0; t < 8; ++t) {
        const uint4* sh = reinterpret_cast<const uint4*>(EH + (size_t)t * NTILE * D_SP);
        // store prefetched first half, stream second half
#pragma unroll
        for (int j = 0; j < 4; ++j) {
            int u = tid + 256 * j;
            int nl = u >> 3, kq = u & 7;
            *reinterpret_cast<uint4*>(sB + nl * (EPAD * 2) + kq * 16) = er[j];
        }
#pragma unroll
        for (int j = 4; j < 8; ++j) {
            int u = tid + 256 * j;
            int nl = u >> 3, kq = u & 7;
            *reinterpret_cast<uint4*>(sB + nl * (EPAD * 2) + kq * 16) = sh[u];
        }
        __syncthreads();

        // prefetch next tile's first half (hidden behind MMA/epilogue)
        if (t + 1 < 8) {
            const uint4* shn = reinterpret_cast<const uint4*>(EH + (size_t)(t + 1) * NTILE * D_SP);
#pragma unroll
            for (int j = 0; j < 4; ++j) er[j] = shn[tid + 256 * j];
        }

#pragma unroll 1
        for (int jc = 0; jc < 4; ++jc) {
            float acc[8][4];
#pragma unroll
            for (int jn = 0; jn < 8; ++jn)
#pragma unroll
                for (int e = 0; e < 4; ++e) acc[jn][e] = 0.f;

#pragma unroll
            for (int ks = 0; ks < 4; ++ks) {
#pragma unroll
                for (int jn = 0; jn < 8; ++jn) {
                    int nl = jc * 64 + jn * 8 + (lane >> 2);
                    const char* bp = sB + nl * (EPAD * 2) + ks * 32 + (lane & 3) * 8;
                    uint2 bb = *reinterpret_cast<const uint2*>(bp);
                    mma16816(acc[jn], a_hi[ks], bb.x, bb.y);
                }
            }

            const u32 inv_pb = (u32)(255 - (t * 32 + jc * 8));   // 255 - pairidx base
#pragma unroll
            for (int jn = 0; jn < 8; ++jn) {
                const u32 inv_p = inv_pb - (u32)jn;
                float ez0 = ex2f(acc[jn][0]), ez1 = ex2f(acc[jn][1]);
                za += ez0 + ez1;
                u32 kA = (__float_as_uint(fmaxf(ez0, ez1)) & 0xFFFFFF00u) | inv_p;
                if (kA > keysA[TPAIR - 1]) {
#pragma unroll
                    for (int j = 0; j < TPAIR; ++j) {
                        u32 lo = umin(keysA[j], kA);
                        keysA[j] = umax(keysA[j], kA);
                        kA = lo;
                    }
                }
                float ez2 = ex2f(acc[jn][2]), ez3 = ex2f(acc[jn][3]);
                zb += ez2 + ez3;
                u32 kB = (__float_as_uint(fmaxf(ez2, ez3)) & 0xFFFFFF00u) | inv_p;
                if (kB > keysB[TPAIR - 1]) {
#pragma unroll
                    for (int j = 0; j < TPAIR; ++j) {
                        u32 lo = umin(keysB[j], kB);
                        keysB[j] = umax(keysB[j], kB);
                        kB = lo;
                    }
                }
            }
        }
        __syncthreads();
    }

    // ---- emit candidate base columns + Z partials ----
    const int q = lane & 3;
    const size_t taskA = (size_t)c * ROWS_TOT + rowA;
    const size_t taskB = (size_t)c * ROWS_TOT + rowB;
    u32* cA = g_cand + taskA * CAND_ROW + q * TPAIR;
    u32* cB = g_cand + taskB * CAND_ROW + q * TPAIR;
#pragma unroll
    for (int j = 0; j < TPAIR; ++j) {
        u32 pA = 255u - (keysA[j] & 0xFFu);
        u32 pB = 255u - (keysB[j] & 0xFFu);
        cA[j] = ((pA >> 5) << 8) + (((pA >> 3) & 3u) << 6) + ((pA & 7u) << 3) + q * 2;
        cB[j] = ((pB >> 5) << 8) + (((pB >> 3) & 3u) << 6) + ((pB & 7u) << 3) + q * 2;
    }
    g_z[taskA * 4 + q] = za;
    g_z[taskB * 4 + q] = zb;
}

// ---------------- kernel 3: refine — smem-staged exact fp32 dots + top-8 + scatter ----------------
#define ER_STRIDE 17        // float4 units per staged e-row (272B, conflict-free)
__global__ __launch_bounds__(256)
void k_refine(float* __restrict__ out) {
    __shared__ float sh_h[8][64];
    __shared__ u32   sh_c[8][CAND_ROW];
    __shared__ __align__(16) float4 sh_e[8][16 * ER_STRIDE];   // 4352 B per warp
    const int tid = threadIdx.x;
    const int wid = tid >> 5;
    const int lane = tid & 31;
    const size_t task = (size_t)blockIdx.x * 8 + wid;   // 0 .. 49151
    const int c = (int)(task >> 13);
    const int r = (int)(task & 8191);
    const int pool = c_pool[c];

    if (lane < 16)
        *reinterpret_cast<float4*>(&sh_h[wid][lane * 4]) =
            *reinterpret_cast<const float4*>(&g_proj[(size_t)r * PROJ_COLS + c * 64 + lane * 4]);
    sh_c[wid][lane] = g_cand[task * CAND_ROW + lane];
    __syncwarp();

    const float* EP = g_enorm + (size_t)pool * N_POOL * D_SP;
    const float4* h4 = reinterpret_cast<const float4*>(sh_h[wid]);

    int   scol[2];
    float sval[2];
    bool  used[2];

#pragma unroll 1
    for (int b = 0; b < 4; ++b) {
#pragma unroll
        for (int p8 = 0; p8 < 8; ++p8) {
            int base = (int)sh_c[wid][b * 8 + p8];           // even col; 512B block
            float4 v = reinterpret_cast<const float4*>(EP + (size_t)base * D_SP)[lane];
            int lrow = 2 * p8 + (lane >> 4);                 // local cand row 0..15
            sh_e[wid][lrow * ER_STRIDE + (lane & 15)] = v;
        }
        __syncwarp();

        const int half = b & 1;
        const int k = b >> 1;
        if ((lane >> 4) == half) {
            const int l15 = lane & 15;
            const int s = b * 16 + l15;
            const float4* e4 = &sh_e[wid][l15 * ER_STRIDE];
            float a = 0.f;
#pragma unroll
            for (int i = 0; i < 16; ++i) {
                float4 e = e4[i], h = h4[i];
                a += h.x * e.x; a += h.y * e.y; a += h.z * e.z; a += h.w * e.w;
            }
            scol[k] = (int)sh_c[wid][s >> 1] + (s & 1);
            sval[k] = a;
            used[k] = false;
        }
        __syncwarp();
    }

    float4 zp = *reinterpret_cast<const float4*>(&g_z[task * 4]);
    const float z = zp.x + zp.y + zp.z + zp.w;

    float rem0 = sval[0], rem1 = sval[1];
    float s8 = 0.f;
#pragma unroll 1
    for (int s = 0; s < 8; ++s) {
        float bv = rem0; int bi = scol[0];
        if (rem1 > bv || (rem1 == bv && scol[1] < bi)) { bv = rem1; bi = scol[1]; }
#pragma unroll
        for (int o = 16; o > 0; o >>= 1) {
            float ov = __shfl_xor_sync(0xffffffffu, bv, o);
            int   oi = __shfl_xor_sync(0xffffffffu, bi, o);
            if (ov > bv || (ov == bv && oi < bi)) { bv = ov; bi = oi; }
        }
        s8 += __expf(bv);
        if (bi == scol[0] && !used[0]) { used[0] = true; rem0 = -FLT_MAX; }
        else if (bi == scol[1] && !used[1]) { used[1] = true; rem1 = -FLT_MAX; }
    }
    const float inv = 1.0f / (s8 + 1e-8f * z);

    float* orow = out + task * (size_t)N_POOL;
    float4* o4 = reinterpret_cast<float4*>(orow);
    const float4 zz = make_float4(0.f, 0.f, 0.f, 0.f);
#pragma unroll
    for (int i = 0; i < 16; ++i) o4[lane + 32 * i] = zz;
    __syncwarp();
    if (used[0]) orow[scol[0]] = __expf(sval[0]) * inv;
    if (used[1]) orow[scol[1]] = __expf(sval[1]) * inv;
}

// ---------------- launch (k_pc deliberately placed as launch #4 for ncu) ----------------
extern "C" void kernel_launch(void* const* d_in, const int* in_sizes, int n_in,
                              void* d_out, int out_size) {
    (void)in_sizes; (void)n_in; (void)out_size;
    const float* x   = (const float*)d_in[0];   // (4,2048,1024)
    const float* W   = (const float*)d_in[1];   // (1024,384)
    const float* b   = (const float*)d_in[2];   // (384,)
    const float* emb = (const float*)d_in[3];   // (10240,64)
    float* out = (float*)d_out;                 // (6,4,2048,2048)

    k_pre<<<1, 1>>>();                                           // launch 1
    k_norm<<<128, 256>>>(emb);                                   // launch 2
    k_pre<<<1, 1>>>();                                           // launch 3 (slot shim)
    k_pc<<<dim3(ROWS_TOT / MROWS, 6), 256, SMEM_BYTES>>>(x, W, b); // launch 4 -> profiled
    k_refine<<<6 * ROWS_TOT / 8, 256>>>(out);                    // launch 5
}